// round 14
// baseline (speedup 1.0000x reference)
#include <cuda_runtime.h>

#define FF 16
#define SS 28
#define B_ 1024
#define NBLK (B_ * 2)
#define NPROD 9

// Effective affine map: out[b,co,d,h,w] = sum_i E[co,i,fd,fh,fw]*x[b,i] + B[co,fd,fh,fw]
__device__ float g_E[3 * 3 * 5 * 5 * 5];   // 1125
__device__ float g_B[3 * 5 * 5 * 5];       // 375
__device__ int          g_prod_cnt = 0;    // producers finished (0..9)
__device__ unsigned int g_done_cnt = 0;    // blocks finished (for replay reset)

__device__ __forceinline__ int fcls(int p, int n) {
    int c = 2;
    if (p == 0)          c = 0;
    else if (p == 1)     c = 1;
    else if (p == n - 1) c = 4;
    else if (p == n - 2) c = 3;
    return c;
}

// conv1 3-class mask: class 0 drops tap k=0, class 2 drops tap k=2.
__device__ __forceinline__ float mask3(int c, int k) {
    return ((c == 0 && k == 0) || (c == 2 && k == 2)) ? 0.f : 1.f;
}

// ---------------------------------------------------------------------------
// Producer body (blocks 0-8): computes one 125-element slice of E (and B for
// blocks 0-2). __noinline__ so its register demand cannot inflate the hot
// consumer path's allocation (R13 regression: regs 40 -> occ 54%).
// ---------------------------------------------------------------------------
__device__ __noinline__ void produce_tables(
        int blk, int tid,
        const float* __restrict__ w1, const float* __restrict__ b1,
        const float* __restrict__ w2, const float* __restrict__ b2) {
    __shared__ float sw1[324], sw2[324], S1[324];
    __shared__ float sb1[4], sb2[3];

    for (int e = tid; e < 324; e += 224) { sw1[e] = w1[e]; sw2[e] = w2[e]; }
    if (tid < 4) sb1[tid] = b1[tid];
    if (tid < 3) sb2[tid] = b2[tid];
    __syncthreads();

    // S1[o][i][cd*9+ch*3+cw]: branch-free masked tap-sums of w1.
    for (int e = tid; e < 324; e += 224) {
        int cw = e % 3, ch = (e / 3) % 3, cd = (e / 9) % 3;
        int base = (e / 27) * 27;
        float s = 0.f;
#pragma unroll
        for (int kd = 0; kd < 3; kd++) {
            float md = mask3(cd, kd);
#pragma unroll
            for (int kh = 0; kh < 3; kh++) {
                float mh = md * mask3(ch, kh);
#pragma unroll
                for (int kw = 0; kw < 3; kw++)
                    s += mh * mask3(cw, kw) * sw1[base + kd * 9 + kh * 3 + kw];
            }
        }
        S1[e] = s;
    }
    __syncthreads();

    if (tid < 125) {
        const int fw = tid % 5, fh = (tid / 5) % 5, fd = tid / 25;

        float vaD[3], vaH[3], vaW[3];
        int   nbD[3], nbH[3], nbW[3];
#pragma unroll
        for (int tt = 0; tt < 3; tt++) {
            vaD[tt] = ((fd == 0 && tt == 0) || (fd == 4 && tt == 2)) ? 0.f : 1.f;
            vaH[tt] = ((fh == 0 && tt == 0) || (fh == 4 && tt == 2)) ? 0.f : 1.f;
            vaW[tt] = ((fw == 0 && tt == 0) || (fw == 4 && tt == 2)) ? 0.f : 1.f;
            int pd = fd + tt - 1; nbD[tt] = (pd == 0) ? 0 : (pd == 4) ? 2 : 1;
            int ph = fh + tt - 1; nbH[tt] = (ph == 0) ? 0 : (ph == 4) ? 2 : 1;
            int pw = fw + tt - 1; nbW[tt] = (pw == 0) ? 0 : (pw == 4) ? 2 : 1;
        }

        {   // E slice: element blk*125 + tid;  i = blk%3, co = blk/3.
            const int i  = blk % 3;
            const int co = blk / 3;
            float a0 = 0.f, a1 = 0.f, a2 = 0.f, a3 = 0.f;
#pragma unroll
            for (int td = 0; td < 3; td++) {
                float cD = vaD[td]; int cd9 = nbD[td] * 9;
#pragma unroll
                for (int th = 0; th < 3; th++) {
                    float cH = cD * vaH[th]; int ch3 = cd9 + nbH[th] * 3;
#pragma unroll
                    for (int tw = 0; tw < 3; tw++) {
                        float coef = cH * vaW[tw];
                        int w2i = co * 108 + td * 9 + th * 3 + tw;   // + o*27
                        int s1i = i * 27 + ch3 + nbW[tw];            // + o*81
                        a0 += coef * sw2[w2i      ] * S1[s1i      ];
                        a1 += coef * sw2[w2i +  27] * S1[s1i +  81];
                        a2 += coef * sw2[w2i +  54] * S1[s1i + 162];
                        a3 += coef * sw2[w2i +  81] * S1[s1i + 243];
                    }
                }
            }
            g_E[blk * 125 + tid] = (a0 + a1) + (a2 + a3);
        }

        if (blk < 3) {   // B: blocks 0-2 own co = blk.
            const int co = blk;
            float s = sb2[co];
#pragma unroll
            for (int o = 0; o < 4; o++) {
                float ws = 0.f;
#pragma unroll
                for (int td = 0; td < 3; td++) {
#pragma unroll
                    for (int th = 0; th < 3; th++) {
                        float cH = vaD[td] * vaH[th];
#pragma unroll
                        for (int tw = 0; tw < 3; tw++)
                            ws += cH * vaW[tw] * sw2[co * 108 + o * 27 + td * 9 + th * 3 + tw];
                    }
                }
                s += sb1[o] * ws;
            }
            g_B[blk * 125 + tid] = s;
        }
    }

    // Release: fence stores, then one thread signals.
    __threadfence();
    __syncthreads();
    if (tid == 0) atomicAdd(&g_prod_cnt, 1);
}

// ---------------------------------------------------------------------------
// SINGLE fused kernel, grid 2048 x 224, minBlocksPerSM=9 to pin regs<=32 so
// the store phase keeps R8's ~71% occupancy.
// ---------------------------------------------------------------------------
__global__ void __launch_bounds__(224, 9) fused_kernel(
        const float* __restrict__ x,
        const float* __restrict__ w1, const float* __restrict__ b1,
        const float* __restrict__ w2, const float* __restrict__ b2,
        float4* __restrict__ out) {
    __shared__ float v[375];           // v[co*125 + fd*25 + fh*5 + fw]
    const int blk = blockIdx.x;
    const int b   = blk >> 1;
    const int p   = blk & 1;           // d-half: 0 -> d 0..7, 1 -> d 8..15
    const int tid = threadIdx.x;

    // x loads are independent of the tables — issue before any waiting.
    float x0 = __ldg(&x[b * 3 + 0]);
    float x1 = __ldg(&x[b * 3 + 1]);
    float x2 = __ldg(&x[b * 3 + 2]);

    if (blk < NPROD) produce_tables(blk, tid, w1, b1, w2, b2);

    // Wait until all 9 table slices are published (lane-0 spin + backoff).
    if (tid == 0) {
        while (*(volatile int*)&g_prod_cnt < NPROD) __nanosleep(64);
    }
    __syncthreads();
    __threadfence();   // acquire: order table reads after flag observation

    // ---------------- expand (exact R8 26.5us body) ----------------------
    for (int e = tid; e < 375; e += 224) {
        int co = e / 125;
        int sp = e - co * 125;
        int eb = co * 375 + sp;        // i stride = 125 in g_E
        v[e] = g_B[e] + x0 * g_E[eb] + x1 * g_E[eb + 125] + x2 * g_E[eb + 250];
    }
    __syncthreads();

    if (tid < 196) {
        int h  = tid / 7;
        int w4 = tid - h * 7;
        int fh = fcls(h, SS);
        int i0 = (w4 == 0) ? 0 : 2;
        int i1 = (w4 == 0) ? 1 : 2;
        int i2 = (w4 == 6) ? 3 : 2;
        int i3 = (w4 == 6) ? 4 : 2;
        int base = fh * 5;

        const int dcls0[8] = {0,1,2,2,2,2,2,2};
        const int dcls1[8] = {2,2,2,2,2,2,3,4};

        float4* op = out + (size_t)b * (3 * FF * 196) + (size_t)p * (8 * 196) + tid;
#pragma unroll
        for (int co = 0; co < 3; co++) {
#pragma unroll
            for (int dd = 0; dd < 8; dd++) {
                int fd = p ? dcls1[dd] : dcls0[dd];
                const float* vv = v + co * 125 + fd * 25 + base;
                float4 o4 = make_float4(vv[i0], vv[i1], vv[i2], vv[i3]);
                op[(co * FF + dd) * 196] = o4;
            }
        }
    }

    // ---------------- replay reset: last block restores counters ---------
    __syncthreads();
    if (tid == 0) {
        unsigned int done = atomicAdd(&g_done_cnt, 1);
        if (done == NBLK - 1) {
            g_prod_cnt = 0;
            g_done_cnt = 0;
            __threadfence();
        }
    }
}

extern "C" void kernel_launch(void* const* d_in, const int* in_sizes, int n_in,
                              void* d_out, int out_size) {
    const float* x  = (const float*)d_in[0];
    const float* w1 = (const float*)d_in[1];
    const float* b1 = (const float*)d_in[2];
    const float* w2 = (const float*)d_in[3];
    const float* b2 = (const float*)d_in[4];

    fused_kernel<<<NBLK, 224>>>(x, w1, b1, w2, b2, (float4*)d_out);
}

// round 15
// speedup vs baseline: 1.1143x; 1.1143x over previous
#include <cuda_runtime.h>

#define FF 16
#define SS 28
#define B_ 1024

// Effective affine map: out[b,co,d,h,w] = sum_i E[co,i,fd,fh,fw]*x[b,i] + B[co,fd,fh,fw]
__device__ float g_E[3 * 3 * 5 * 5 * 5];   // 1125
__device__ float g_B[3 * 5 * 5 * 5];       // 375

__device__ __forceinline__ int fcls(int p, int n) {
    int c = 2;
    if (p == 0)          c = 0;
    else if (p == 1)     c = 1;
    else if (p == n - 1) c = 4;
    else if (p == n - 2) c = 3;
    return c;
}

// conv1 3-class mask: class 0 drops tap k=0, class 2 drops tap k=2.
__device__ __forceinline__ float mask3(int c, int k) {
    return ((c == 0 && k == 0) || (c == 2 && k == 2)) ? 0.f : 1.f;
}

// ---------------------------------------------------------------------------
// Precompute E and Beff (measured-good R8 form): 9 blocks x 352 threads, one
// element per thread, 4 independent accumulators, PDL release at end.
// ---------------------------------------------------------------------------
__global__ void __launch_bounds__(352) precompute_kernel(
        const float* __restrict__ w1, const float* __restrict__ b1,
        const float* __restrict__ w2, const float* __restrict__ b2) {
    __shared__ float sw1[324], sw2[324], S1[324];
    __shared__ float sb1[4], sb2[3];
    const int t   = threadIdx.x;
    const int blk = blockIdx.x;

    if (t < 324) { sw1[t] = w1[t]; sw2[t] = w2[t]; }
    if (t < 4) sb1[t] = b1[t];
    if (t < 3) sb2[t] = b2[t];
    __syncthreads();

    if (t < 324) {
        int cw = t % 3, ch = (t / 3) % 3, cd = (t / 9) % 3;
        int base = (t / 27) * 27;
        float s = 0.f;
#pragma unroll
        for (int kd = 0; kd < 3; kd++) {
            float md = mask3(cd, kd);
#pragma unroll
            for (int kh = 0; kh < 3; kh++) {
                float mh = md * mask3(ch, kh);
#pragma unroll
                for (int kw = 0; kw < 3; kw++)
                    s += mh * mask3(cw, kw) * sw1[base + kd * 9 + kh * 3 + kw];
            }
        }
        S1[t] = s;
    }
    __syncthreads();

    if (t < 125) {
        const int fw = t % 5, fh = (t / 5) % 5, fd = t / 25;

        float vaD[3], vaH[3], vaW[3];
        int   nbD[3], nbH[3], nbW[3];
#pragma unroll
        for (int tt = 0; tt < 3; tt++) {
            vaD[tt] = ((fd == 0 && tt == 0) || (fd == 4 && tt == 2)) ? 0.f : 1.f;
            vaH[tt] = ((fh == 0 && tt == 0) || (fh == 4 && tt == 2)) ? 0.f : 1.f;
            vaW[tt] = ((fw == 0 && tt == 0) || (fw == 4 && tt == 2)) ? 0.f : 1.f;
            int pd = fd + tt - 1; nbD[tt] = (pd == 0) ? 0 : (pd == 4) ? 2 : 1;
            int ph = fh + tt - 1; nbH[tt] = (ph == 0) ? 0 : (ph == 4) ? 2 : 1;
            int pw = fw + tt - 1; nbW[tt] = (pw == 0) ? 0 : (pw == 4) ? 2 : 1;
        }

        {
            const int i  = blk % 3;
            const int co = blk / 3;
            float a0 = 0.f, a1 = 0.f, a2 = 0.f, a3 = 0.f;
#pragma unroll
            for (int td = 0; td < 3; td++) {
                float cD = vaD[td]; int cd9 = nbD[td] * 9;
#pragma unroll
                for (int th = 0; th < 3; th++) {
                    float cH = cD * vaH[th]; int ch3 = cd9 + nbH[th] * 3;
#pragma unroll
                    for (int tw = 0; tw < 3; tw++) {
                        float coef = cH * vaW[tw];
                        int w2i = co * 108 + td * 9 + th * 3 + tw;   // + o*27
                        int s1i = i * 27 + ch3 + nbW[tw];            // + o*81
                        a0 += coef * sw2[w2i      ] * S1[s1i      ];
                        a1 += coef * sw2[w2i +  27] * S1[s1i +  81];
                        a2 += coef * sw2[w2i +  54] * S1[s1i + 162];
                        a3 += coef * sw2[w2i +  81] * S1[s1i + 243];
                    }
                }
            }
            g_E[blk * 125 + t] = (a0 + a1) + (a2 + a3);
        }

        if (blk < 3) {
            const int co = blk;
            float s = sb2[co];
#pragma unroll
            for (int o = 0; o < 4; o++) {
                float ws = 0.f;
#pragma unroll
                for (int td = 0; td < 3; td++) {
#pragma unroll
                    for (int th = 0; th < 3; th++) {
                        float cH = vaD[td] * vaH[th];
#pragma unroll
                        for (int tw = 0; tw < 3; tw++)
                            ws += cH * vaW[tw] * sw2[co * 108 + o * 27 + td * 9 + th * 3 + tw];
                    }
                }
                s += sb1[o] * ws;
            }
            g_B[blk * 125 + t] = s;
        }
    }

    __threadfence();
    asm volatile("griddepcontrol.launch_dependents;" ::: "memory");
}

// ---------------------------------------------------------------------------
// Expand, ALL-LANES-STORE version. Per block (b, d-half): 24 slabs x 196
// float4 = 4704 = 21 x 224, so every thread stores 21 float4s (vs 196/224
// threads x 48 before — +14% store lanes per SM). Thread t owns linear
// indices L = k*224 + t; since 224 = 196 + 28 the (slab, pos) decomposition
// updates incrementally, and w4 = t%7 is constant so the fw-selects stay
// per-thread constants.
// ---------------------------------------------------------------------------
__global__ void __launch_bounds__(224) expand_kernel(const float* __restrict__ x,
                                                     float4* __restrict__ out) {
    __shared__ float v[375];           // v[co*125 + fd*25 + fh*5 + fw]
    const int blk = blockIdx.x;
    const int b   = blk >> 1;
    const int p   = blk & 1;           // d-half: 0 -> d 0..7, 1 -> d 8..15
    const int tid = threadIdx.x;

    float x0 = __ldg(&x[b * 3 + 0]);
    float x1 = __ldg(&x[b * 3 + 1]);
    float x2 = __ldg(&x[b * 3 + 2]);

    asm volatile("griddepcontrol.wait;" ::: "memory");

    for (int e = tid; e < 375; e += 224) {
        int co = e / 125;
        int sp = e - co * 125;
        int eb = co * 375 + sp;        // i stride = 125 in g_E
        v[e] = g_B[e] + x0 * g_E[eb] + x1 * g_E[eb + 125] + x2 * g_E[eb + 250];
    }
    __syncthreads();

    // Per-thread constants.
    const int w4 = tid % 7;            // pos % 7 is invariant (196 and 28 ≡ 0 mod 7)
    const int i0 = (w4 == 0) ? 0 : 2;
    const int i1 = (w4 == 0) ? 1 : 2;
    const int i2 = (w4 == 6) ? 3 : 2;
    const int i3 = (w4 == 6) ? 4 : 2;

    int pos  = (tid < 196) ? tid : tid - 196;   // position within slab [0,196)
    int slab = (tid < 196) ? 0 : 1;             // slab = co*8 + dd  [0,24)

    float4* base4 = out + (size_t)b * (3 * FF * 196) + (size_t)p * (8 * 196);

#pragma unroll
    for (int k = 0; k < 21; k++) {
        int h  = pos / 7;              // constant-divisor -> mulhi
        int fh = fcls(h, SS);
        int co = slab >> 3;
        int dd = slab & 7;
        // fd: half 0 -> d=dd:   0,1,2,2,...   half 1 -> d=8+dd: 2,...,2,3,4
        int fd = p ? ((dd <= 5) ? 2 : (dd - 3)) : ((dd < 2) ? dd : 2);
        const float* vv = v + co * 125 + fd * 25 + fh * 5;
        float4 o4 = make_float4(vv[i0], vv[i1], vv[i2], vv[i3]);
        base4[co * (FF * 196) + dd * 196 + pos] = o4;

        // Advance L by 224 = 1 slab + 28 positions (with wrap).
        pos  += 28;
        slab += 1;
        if (pos >= 196) { pos -= 196; slab += 1; }
    }
}

extern "C" void kernel_launch(void* const* d_in, const int* in_sizes, int n_in,
                              void* d_out, int out_size) {
    const float* x  = (const float*)d_in[0];
    const float* w1 = (const float*)d_in[1];
    const float* b1 = (const float*)d_in[2];
    const float* w2 = (const float*)d_in[3];
    const float* b2 = (const float*)d_in[4];

    precompute_kernel<<<9, 352>>>(w1, b1, w2, b2);

    cudaLaunchConfig_t cfg = {};
    cfg.gridDim  = dim3(B_ * 2, 1, 1);
    cfg.blockDim = dim3(224, 1, 1);
    cudaLaunchAttribute attr[1];
    attr[0].id = cudaLaunchAttributeProgrammaticStreamSerialization;
    attr[0].val.programmaticStreamSerializationAllowed = 1;
    cfg.attrs    = attr;
    cfg.numAttrs = 1;
    cudaLaunchKernelEx(&cfg, expand_kernel, x, (float4*)d_out);
}

// round 16
// speedup vs baseline: 1.1885x; 1.0667x over previous
#include <cuda_runtime.h>

#define FF 16
#define SS 28
#define B_ 1024

// Effective affine map: out[b,co,d,h,w] = sum_i E[co,i,fd,fh,fw]*x[b,i] + B[co,fd,fh,fw]
__device__ float g_E[3 * 3 * 5 * 5 * 5];   // 1125
__device__ float g_B[3 * 5 * 5 * 5];       // 375

__device__ __forceinline__ int fcls(int p, int n) {
    int c = 2;
    if (p == 0)          c = 0;
    else if (p == 1)     c = 1;
    else if (p == n - 1) c = 4;
    else if (p == n - 2) c = 3;
    return c;
}

// conv1 3-class mask: class 0 drops tap k=0, class 2 drops tap k=2.
__device__ __forceinline__ float mask3(int c, int k) {
    return ((c == 0 && k == 0) || (c == 2 && k == 2)) ? 0.f : 1.f;
}

// ---------------------------------------------------------------------------
// Precompute E and Beff (measured-good form): 9 blocks x 352 threads, one
// element per thread, 4 independent accumulators, PDL release at end.
// ---------------------------------------------------------------------------
__global__ void __launch_bounds__(352) precompute_kernel(
        const float* __restrict__ w1, const float* __restrict__ b1,
        const float* __restrict__ w2, const float* __restrict__ b2) {
    __shared__ float sw1[324], sw2[324], S1[324];
    __shared__ float sb1[4], sb2[3];
    const int t   = threadIdx.x;
    const int blk = blockIdx.x;

    if (t < 324) { sw1[t] = w1[t]; sw2[t] = w2[t]; }
    if (t < 4) sb1[t] = b1[t];
    if (t < 3) sb2[t] = b2[t];
    __syncthreads();

    if (t < 324) {
        int cw = t % 3, ch = (t / 3) % 3, cd = (t / 9) % 3;
        int base = (t / 27) * 27;
        float s = 0.f;
#pragma unroll
        for (int kd = 0; kd < 3; kd++) {
            float md = mask3(cd, kd);
#pragma unroll
            for (int kh = 0; kh < 3; kh++) {
                float mh = md * mask3(ch, kh);
#pragma unroll
                for (int kw = 0; kw < 3; kw++)
                    s += mh * mask3(cw, kw) * sw1[base + kd * 9 + kh * 3 + kw];
            }
        }
        S1[t] = s;
    }
    __syncthreads();

    if (t < 125) {
        const int fw = t % 5, fh = (t / 5) % 5, fd = t / 25;

        float vaD[3], vaH[3], vaW[3];
        int   nbD[3], nbH[3], nbW[3];
#pragma unroll
        for (int tt = 0; tt < 3; tt++) {
            vaD[tt] = ((fd == 0 && tt == 0) || (fd == 4 && tt == 2)) ? 0.f : 1.f;
            vaH[tt] = ((fh == 0 && tt == 0) || (fh == 4 && tt == 2)) ? 0.f : 1.f;
            vaW[tt] = ((fw == 0 && tt == 0) || (fw == 4 && tt == 2)) ? 0.f : 1.f;
            int pd = fd + tt - 1; nbD[tt] = (pd == 0) ? 0 : (pd == 4) ? 2 : 1;
            int ph = fh + tt - 1; nbH[tt] = (ph == 0) ? 0 : (ph == 4) ? 2 : 1;
            int pw = fw + tt - 1; nbW[tt] = (pw == 0) ? 0 : (pw == 4) ? 2 : 1;
        }

        {
            const int i  = blk % 3;
            const int co = blk / 3;
            float a0 = 0.f, a1 = 0.f, a2 = 0.f, a3 = 0.f;
#pragma unroll
            for (int td = 0; td < 3; td++) {
                float cD = vaD[td]; int cd9 = nbD[td] * 9;
#pragma unroll
                for (int th = 0; th < 3; th++) {
                    float cH = cD * vaH[th]; int ch3 = cd9 + nbH[th] * 3;
#pragma unroll
                    for (int tw = 0; tw < 3; tw++) {
                        float coef = cH * vaW[tw];
                        int w2i = co * 108 + td * 9 + th * 3 + tw;   // + o*27
                        int s1i = i * 27 + ch3 + nbW[tw];            // + o*81
                        a0 += coef * sw2[w2i      ] * S1[s1i      ];
                        a1 += coef * sw2[w2i +  27] * S1[s1i +  81];
                        a2 += coef * sw2[w2i +  54] * S1[s1i + 162];
                        a3 += coef * sw2[w2i +  81] * S1[s1i + 243];
                    }
                }
            }
            g_E[blk * 125 + t] = (a0 + a1) + (a2 + a3);
        }

        if (blk < 3) {
            const int co = blk;
            float s = sb2[co];
#pragma unroll
            for (int o = 0; o < 4; o++) {
                float ws = 0.f;
#pragma unroll
                for (int td = 0; td < 3; td++) {
#pragma unroll
                    for (int th = 0; th < 3; th++) {
                        float cH = vaD[td] * vaH[th];
#pragma unroll
                        for (int tw = 0; tw < 3; tw++)
                            ws += cH * vaW[tw] * sw2[co * 108 + o * 27 + td * 9 + th * 3 + tw];
                    }
                }
                s += sb1[o] * ws;
            }
            g_B[blk * 125 + t] = s;
        }
    }

    __threadfence();
    asm volatile("griddepcontrol.launch_dependents;" ::: "memory");
}

// ---------------------------------------------------------------------------
// Expand via TMA BULK STORES. Grid 6144 = (b, co, p); each block owns ONE
// contiguous 25088-byte output chunk (8 d-slices x 196 float4):
//   1. v[125]: this co's distinct values (one per thread).
//   2. Build the chunk in SMEM: 7 STS.128 per thread (issue-only, no L1tex
//      wavefront result path).
//   3. ONE cp.async.bulk SMEM->GMEM per block: the store stream leaves the
//      SM's STG/L1 path entirely and rides the TMA engine (~6300 B/cyc chip).
// ---------------------------------------------------------------------------
__global__ void __launch_bounds__(224) expand_kernel(const float* __restrict__ x,
                                                     float4* __restrict__ out) {
    __shared__ alignas(16) float4 buf[1568];   // 8*196 float4 = 25088 B
    __shared__ float v[125];                   // this co: v[fd*25 + fh*5 + fw]
    const int blk = blockIdx.x;
    const int b   = blk / 6;
    const int r   = blk - b * 6;
    const int co  = r >> 1;
    const int p   = r & 1;                     // d-half: 0 -> d 0..7, 1 -> d 8..15
    const int tid = threadIdx.x;

    float x0 = __ldg(&x[b * 3 + 0]);
    float x1 = __ldg(&x[b * 3 + 1]);
    float x2 = __ldg(&x[b * 3 + 2]);

    asm volatile("griddepcontrol.wait;" ::: "memory");

    if (tid < 125) {
        int eb = co * 375 + tid;               // i stride = 125 in g_E
        v[tid] = g_B[co * 125 + tid] + x0 * g_E[eb] + x1 * g_E[eb + 125] + x2 * g_E[eb + 250];
    }
    __syncthreads();

    // Build the 1568-float4 chunk: s = tid + k*224, k = 0..6.
    // w4 = s % 7 == tid % 7 (224 ≡ 0 mod 7) -> fw-selects are per-thread consts.
    const int w4 = tid % 7;
    const int i0 = (w4 == 0) ? 0 : 2;
    const int i1 = (w4 == 0) ? 1 : 2;
    const int i2 = (w4 == 6) ? 3 : 2;
    const int i3 = (w4 == 6) ? 4 : 2;

#pragma unroll
    for (int k = 0; k < 7; k++) {
        int s   = tid + k * 224;
        int dd  = s / 196;
        int pos = s - dd * 196;
        int h   = pos / 7;
        int fh  = fcls(h, SS);
        // fd: half 0 -> d=dd: 0,1,2,...   half 1 -> d=8+dd: 2,...,2,3,4
        int fd  = p ? ((dd <= 5) ? 2 : (dd - 3)) : ((dd < 2) ? dd : 2);
        const float* vv = v + fd * 25 + fh * 5;
        buf[s] = make_float4(vv[i0], vv[i1], vv[i2], vv[i3]);
    }
    __syncthreads();

    // One bulk store per block: SMEM -> contiguous GMEM chunk.
    if (tid == 0) {
        float4* dst = out + (size_t)b * (3 * FF * 196) + (size_t)co * (FF * 196)
                          + (size_t)p * (8 * 196);
        unsigned int src = (unsigned int)__cvta_generic_to_shared(buf);
        asm volatile(
            "cp.async.bulk.global.shared::cta.bulk_group [%0], [%1], %2;\n\t"
            "cp.async.bulk.commit_group;\n\t"
            "cp.async.bulk.wait_group.read 0;"
            :: "l"(dst), "r"(src), "r"(25088)
            : "memory");
    }
}

extern "C" void kernel_launch(void* const* d_in, const int* in_sizes, int n_in,
                              void* d_out, int out_size) {
    const float* x  = (const float*)d_in[0];
    const float* w1 = (const float*)d_in[1];
    const float* b1 = (const float*)d_in[2];
    const float* w2 = (const float*)d_in[3];
    const float* b2 = (const float*)d_in[4];

    precompute_kernel<<<9, 352>>>(w1, b1, w2, b2);

    cudaLaunchConfig_t cfg = {};
    cfg.gridDim  = dim3(B_ * 6, 1, 1);
    cfg.blockDim = dim3(224, 1, 1);
    cudaLaunchAttribute attr[1];
    attr[0].id = cudaLaunchAttributeProgrammaticStreamSerialization;
    attr[0].val.programmaticStreamSerializationAllowed = 1;
    cfg.attrs    = attr;
    cfg.numAttrs = 1;
    cudaLaunchKernelEx(&cfg, expand_kernel, x, (float4*)d_out);
}

// round 17
// speedup vs baseline: 1.1898x; 1.0010x over previous
#include <cuda_runtime.h>

#define FF 16
#define SS 28
#define B_ 1024

// Effective affine map: out[b,co,d,h,w] = sum_i E[co,i,fd,fh,fw]*x[b,i] + B[co,fd,fh,fw]
__device__ float g_E[3 * 3 * 5 * 5 * 5];   // 1125
__device__ float g_B[3 * 5 * 5 * 5];       // 375

__device__ __forceinline__ int fcls(int p, int n) {
    int c = 2;
    if (p == 0)          c = 0;
    else if (p == 1)     c = 1;
    else if (p == n - 1) c = 4;
    else if (p == n - 2) c = 3;
    return c;
}

// conv1 3-class mask: class 0 drops tap k=0, class 2 drops tap k=2.
__device__ __forceinline__ float mask3(int c, int k) {
    return ((c == 0 && k == 0) || (c == 2 && k == 2)) ? 0.f : 1.f;
}

// ---------------------------------------------------------------------------
// Precompute E and Beff (measured-good form): 9 blocks x 352 threads, one
// element per thread, 4 independent accumulators, PDL release at end.
// ---------------------------------------------------------------------------
__global__ void __launch_bounds__(352) precompute_kernel(
        const float* __restrict__ w1, const float* __restrict__ b1,
        const float* __restrict__ w2, const float* __restrict__ b2) {
    __shared__ float sw1[324], sw2[324], S1[324];
    __shared__ float sb1[4], sb2[3];
    const int t   = threadIdx.x;
    const int blk = blockIdx.x;

    if (t < 324) { sw1[t] = w1[t]; sw2[t] = w2[t]; }
    if (t < 4) sb1[t] = b1[t];
    if (t < 3) sb2[t] = b2[t];
    __syncthreads();

    if (t < 324) {
        int cw = t % 3, ch = (t / 3) % 3, cd = (t / 9) % 3;
        int base = (t / 27) * 27;
        float s = 0.f;
#pragma unroll
        for (int kd = 0; kd < 3; kd++) {
            float md = mask3(cd, kd);
#pragma unroll
            for (int kh = 0; kh < 3; kh++) {
                float mh = md * mask3(ch, kh);
#pragma unroll
                for (int kw = 0; kw < 3; kw++)
                    s += mh * mask3(cw, kw) * sw1[base + kd * 9 + kh * 3 + kw];
            }
        }
        S1[t] = s;
    }
    __syncthreads();

    if (t < 125) {
        const int fw = t % 5, fh = (t / 5) % 5, fd = t / 25;

        float vaD[3], vaH[3], vaW[3];
        int   nbD[3], nbH[3], nbW[3];
#pragma unroll
        for (int tt = 0; tt < 3; tt++) {
            vaD[tt] = ((fd == 0 && tt == 0) || (fd == 4 && tt == 2)) ? 0.f : 1.f;
            vaH[tt] = ((fh == 0 && tt == 0) || (fh == 4 && tt == 2)) ? 0.f : 1.f;
            vaW[tt] = ((fw == 0 && tt == 0) || (fw == 4 && tt == 2)) ? 0.f : 1.f;
            int pd = fd + tt - 1; nbD[tt] = (pd == 0) ? 0 : (pd == 4) ? 2 : 1;
            int ph = fh + tt - 1; nbH[tt] = (ph == 0) ? 0 : (ph == 4) ? 2 : 1;
            int pw = fw + tt - 1; nbW[tt] = (pw == 0) ? 0 : (pw == 4) ? 2 : 1;
        }

        {
            const int i  = blk % 3;
            const int co = blk / 3;
            float a0 = 0.f, a1 = 0.f, a2 = 0.f, a3 = 0.f;
#pragma unroll
            for (int td = 0; td < 3; td++) {
                float cD = vaD[td]; int cd9 = nbD[td] * 9;
#pragma unroll
                for (int th = 0; th < 3; th++) {
                    float cH = cD * vaH[th]; int ch3 = cd9 + nbH[th] * 3;
#pragma unroll
                    for (int tw = 0; tw < 3; tw++) {
                        float coef = cH * vaW[tw];
                        int w2i = co * 108 + td * 9 + th * 3 + tw;   // + o*27
                        int s1i = i * 27 + ch3 + nbW[tw];            // + o*81
                        a0 += coef * sw2[w2i      ] * S1[s1i      ];
                        a1 += coef * sw2[w2i +  27] * S1[s1i +  81];
                        a2 += coef * sw2[w2i +  54] * S1[s1i + 162];
                        a3 += coef * sw2[w2i +  81] * S1[s1i + 243];
                    }
                }
            }
            g_E[blk * 125 + t] = (a0 + a1) + (a2 + a3);
        }

        if (blk < 3) {
            const int co = blk;
            float s = sb2[co];
#pragma unroll
            for (int o = 0; o < 4; o++) {
                float ws = 0.f;
#pragma unroll
                for (int td = 0; td < 3; td++) {
#pragma unroll
                    for (int th = 0; th < 3; th++) {
                        float cH = vaD[td] * vaH[th];
#pragma unroll
                        for (int tw = 0; tw < 3; tw++)
                            ws += cH * vaW[tw] * sw2[co * 108 + o * 27 + td * 9 + th * 3 + tw];
                    }
                }
                s += sb1[o] * ws;
            }
            g_B[blk * 125 + t] = s;
        }
    }

    __threadfence();
    asm volatile("griddepcontrol.launch_dependents;" ::: "memory");
}

// ---------------------------------------------------------------------------
// Expand via TMA bulk stores WITH L2::evict_last cache hint.
// Theory: the 26.4us floor = LTS throughput cap on (store-in + evict-out)
// ≈ (154 + 94.5) MB at ~9.4 TB/s. evict_last biases output lines to stay
// L2-resident across graph replays, shrinking the eviction term toward the
// capacity minimum (~28 MB).
// Grid 6144 = (b, co, p); each block owns one contiguous 25088-B chunk.
// ---------------------------------------------------------------------------
__global__ void __launch_bounds__(224) expand_kernel(const float* __restrict__ x,
                                                     float4* __restrict__ out) {
    __shared__ alignas(16) float4 buf[1568];   // 8*196 float4 = 25088 B
    __shared__ float v[125];                   // this co: v[fd*25 + fh*5 + fw]
    const int blk = blockIdx.x;
    const int b   = blk / 6;
    const int r   = blk - b * 6;
    const int co  = r >> 1;
    const int p   = r & 1;                     // d-half: 0 -> d 0..7, 1 -> d 8..15
    const int tid = threadIdx.x;

    float x0 = __ldg(&x[b * 3 + 0]);
    float x1 = __ldg(&x[b * 3 + 1]);
    float x2 = __ldg(&x[b * 3 + 2]);

    asm volatile("griddepcontrol.wait;" ::: "memory");

    if (tid < 125) {
        int eb = co * 375 + tid;               // i stride = 125 in g_E
        v[tid] = g_B[co * 125 + tid] + x0 * g_E[eb] + x1 * g_E[eb + 125] + x2 * g_E[eb + 250];
    }
    __syncthreads();

    // Build the 1568-float4 chunk: s = tid + k*224, k = 0..6.
    // w4 = s % 7 == tid % 7 (224 ≡ 0 mod 7) -> fw-selects are per-thread consts.
    const int w4 = tid % 7;
    const int i0 = (w4 == 0) ? 0 : 2;
    const int i1 = (w4 == 0) ? 1 : 2;
    const int i2 = (w4 == 6) ? 3 : 2;
    const int i3 = (w4 == 6) ? 4 : 2;

#pragma unroll
    for (int k = 0; k < 7; k++) {
        int s   = tid + k * 224;
        int dd  = s / 196;
        int pos = s - dd * 196;
        int h   = pos / 7;
        int fh  = fcls(h, SS);
        // fd: half 0 -> d=dd: 0,1,2,...   half 1 -> d=8+dd: 2,...,2,3,4
        int fd  = p ? ((dd <= 5) ? 2 : (dd - 3)) : ((dd < 2) ? dd : 2);
        const float* vv = v + fd * 25 + fh * 5;
        buf[s] = make_float4(vv[i0], vv[i1], vv[i2], vv[i3]);
    }
    __syncthreads();

    // One bulk store per block with evict_last L2 policy.
    if (tid == 0) {
        float4* dst = out + (size_t)b * (3 * FF * 196) + (size_t)co * (FF * 196)
                          + (size_t)p * (8 * 196);
        unsigned int src = (unsigned int)__cvta_generic_to_shared(buf);
        unsigned long long pol;
        asm volatile("createpolicy.fractional.L2::evict_last.b64 %0, 1.0;" : "=l"(pol));
        asm volatile(
            "cp.async.bulk.global.shared::cta.bulk_group.L2::cache_hint [%0], [%1], %2, %3;\n\t"
            "cp.async.bulk.commit_group;\n\t"
            "cp.async.bulk.wait_group.read 0;"
            :: "l"(dst), "r"(src), "r"(25088), "l"(pol)
            : "memory");
    }
}

extern "C" void kernel_launch(void* const* d_in, const int* in_sizes, int n_in,
                              void* d_out, int out_size) {
    const float* x  = (const float*)d_in[0];
    const float* w1 = (const float*)d_in[1];
    const float* b1 = (const float*)d_in[2];
    const float* w2 = (const float*)d_in[3];
    const float* b2 = (const float*)d_in[4];

    precompute_kernel<<<9, 352>>>(w1, b1, w2, b2);

    cudaLaunchConfig_t cfg = {};
    cfg.gridDim  = dim3(B_ * 6, 1, 1);
    cfg.blockDim = dim3(224, 1, 1);
    cudaLaunchAttribute attr[1];
    attr[0].id = cudaLaunchAttributeProgrammaticStreamSerialization;
    attr[0].val.programmaticStreamSerializationAllowed = 1;
    cfg.attrs    = attr;
    cfg.numAttrs = 1;
    cudaLaunchKernelEx(&cfg, expand_kernel, x, (float4*)d_out);
}